// round 13
// baseline (speedup 1.0000x reference)
#include <cuda_runtime.h>
#include <math.h>

// Problem constants
#define Bsz 4
#define Ssz 2048
#define Csz 1024
#define Hn  16
#define HSz 64

// Scratch (allocation-free requirement -> __device__ globals)
__device__ float g_q[Bsz * Hn * Ssz * HSz];   // [B,H,S,HS]
__device__ float g_k[Bsz * Hn * Ssz * HSz];
__device__ float g_v[Bsz * Hn * Ssz * HSz];
__device__ float g_att[Bsz * Ssz * Csz];      // [B,S,C] (heads concatenated)

// ---------------------------------------------------------------------------
// Kernel 1: fused QKV projection.
// C_out[m, n] = sum_c x[m, c] * W[n, c-layout], n in [0,3072) = (sel, h, d).
// 128x128x8 tile, 256 threads, 8x8 microtile. Each 128-wide N tile spans
// exactly two heads; per-thread weight pointer is decoded once.
// ---------------------------------------------------------------------------
__global__ __launch_bounds__(256)
void qkv_gemm_kernel(const float* __restrict__ x,
                     const float* __restrict__ Wq,
                     const float* __restrict__ Wk,
                     const float* __restrict__ Wv)
{
    __shared__ float As[8][128];
    __shared__ float Bs[8][128];

    const int tid = threadIdx.x;
    const int m0 = blockIdx.y * 128;
    const int n0 = blockIdx.x * 128;

    // A (x) load mapping: float4 along k
    const int a_row = tid >> 1;          // 0..127
    const int a_k4  = (tid & 1) << 2;    // 0 or 4
    const float* aptr = x + (size_t)(m0 + a_row) * Csz + a_k4;

    // B (weights) load mapping: float4 along n (== d within a head)
    const int b_k  = tid >> 5;           // 0..7
    const int b_n4 = (tid & 31) << 2;    // 0..124
    const int nb   = n0 + b_n4;
    const int sel  = nb >> 10;           // 0=q,1=k,2=v
    const int hh   = (nb >> 6) & (Hn - 1);
    const int dd   = nb & (HSz - 1);
    const float* Wsel = (sel == 0) ? Wq : (sel == 1 ? Wk : Wv);
    const float* wptr = Wsel + (size_t)hh * Csz * HSz + dd;   // + c*HSz

    const int ty4 = (tid >> 4) << 2;     // 0..60
    const int tx4 = (tid & 15) << 2;     // 0..60

    float acc[8][8];
    #pragma unroll
    for (int i = 0; i < 8; i++)
        #pragma unroll
        for (int j = 0; j < 8; j++) acc[i][j] = 0.f;

    for (int k0 = 0; k0 < Csz; k0 += 8) {
        float4 av = *(const float4*)(aptr + k0);
        As[a_k4 + 0][a_row] = av.x;
        As[a_k4 + 1][a_row] = av.y;
        As[a_k4 + 2][a_row] = av.z;
        As[a_k4 + 3][a_row] = av.w;
        float4 bv = *(const float4*)(wptr + (size_t)(k0 + b_k) * HSz);
        *(float4*)&Bs[b_k][b_n4] = bv;
        __syncthreads();

        #pragma unroll
        for (int kk = 0; kk < 8; kk++) {
            float ra[8], rb[8];
            *(float4*)&ra[0] = *(const float4*)&As[kk][ty4];
            *(float4*)&ra[4] = *(const float4*)&As[kk][64 + ty4];
            *(float4*)&rb[0] = *(const float4*)&Bs[kk][tx4];
            *(float4*)&rb[4] = *(const float4*)&Bs[kk][64 + tx4];
            #pragma unroll
            for (int i = 0; i < 8; i++)
                #pragma unroll
                for (int j = 0; j < 8; j++)
                    acc[i][j] += ra[i] * rb[j];
        }
        __syncthreads();
    }

    // Write out in [B,H,S,HS] layout
    #pragma unroll
    for (int cg = 0; cg < 2; cg++) {
        const int nc  = n0 + cg * 64 + tx4;
        const int s2  = nc >> 10;
        const int h2  = (nc >> 6) & (Hn - 1);
        const int d2  = nc & (HSz - 1);
        float* obuf = (s2 == 0) ? g_q : (s2 == 1 ? g_k : g_v);
        #pragma unroll
        for (int rg = 0; rg < 2; rg++) {
            #pragma unroll
            for (int i = 0; i < 4; i++) {
                const int m  = m0 + rg * 64 + ty4 + i;
                const int bb = m >> 11;       // /2048
                const int ss = m & (Ssz - 1);
                float4 o;
                o.x = acc[rg * 4 + i][cg * 4 + 0];
                o.y = acc[rg * 4 + i][cg * 4 + 1];
                o.z = acc[rg * 4 + i][cg * 4 + 2];
                o.w = acc[rg * 4 + i][cg * 4 + 3];
                *(float4*)(obuf + (((size_t)(bb * Hn + h2) * Ssz + ss) * HSz + d2)) = o;
            }
        }
    }
}

// ---------------------------------------------------------------------------
// Kernel 2: flash attention, fp32, causal.
// Block = (qtile, b*H+h). 64 query rows, key tiles of 64, HS=64.
// 256 threads as 16x16; each thread owns a 4x4 patch (rows ty*4, cols tx*4).
// Row groups are 16 consecutive lanes -> shfl_xor reductions.
// ---------------------------------------------------------------------------
#define KSTR 68   // smem row stride (floats): 16B-aligned, conflict-reduced

__global__ __launch_bounds__(256)
void attn_kernel()
{
    extern __shared__ float sm[];
    float* Qt = sm;                  // [64][KSTR]  Q transposed (scaled by 1/8)
    float* Kt = Qt + 64 * KSTR;      // [64][KSTR]  K transposed
    float* Vs = Kt + 64 * KSTR;      // [64][KSTR]  V direct
    float* Pt = Vs + 64 * KSTR;      // [64][KSTR]  P transposed

    const int tid = threadIdx.x;
    const int bh  = blockIdx.y;
    const int q0  = blockIdx.x * 64;

    const float* qg = g_q + (size_t)bh * Ssz * HSz;
    const float* kg = g_k + (size_t)bh * Ssz * HSz;
    const float* vg = g_v + (size_t)bh * Ssz * HSz;

    const int lr  = tid >> 4;          // 0..15
    const int ld4 = (tid & 15) << 2;   // 0..60

    // Load Q tile transposed, pre-scaled by 1/sqrt(HS)
    #pragma unroll
    for (int it = 0; it < 4; it++) {
        const int r = lr + it * 16;
        float4 qv = *(const float4*)(qg + (size_t)(q0 + r) * HSz + ld4);
        Qt[(ld4 + 0) * KSTR + r] = qv.x * 0.125f;
        Qt[(ld4 + 1) * KSTR + r] = qv.y * 0.125f;
        Qt[(ld4 + 2) * KSTR + r] = qv.z * 0.125f;
        Qt[(ld4 + 3) * KSTR + r] = qv.w * 0.125f;
    }

    const int ty4 = (tid >> 4) << 2;
    const int tx4 = (tid & 15) << 2;

    float m_i[4], l_i[4], acc[4][4];
    #pragma unroll
    for (int i = 0; i < 4; i++) {
        m_i[i] = -1e30f;
        l_i[i] = 0.f;
        #pragma unroll
        for (int j = 0; j < 4; j++) acc[i][j] = 0.f;
    }

    const int nkt = blockIdx.x + 1;   // causal: only key tiles <= qtile
    for (int kt = 0; kt < nkt; kt++) {
        const int k0 = kt * 64;
        __syncthreads();   // previous P@V done before overwriting Kt/Vs

        // Load K (transposed) and V (direct)
        #pragma unroll
        for (int it = 0; it < 4; it++) {
            const int c = lr + it * 16;
            float4 kv = *(const float4*)(kg + (size_t)(k0 + c) * HSz + ld4);
            Kt[(ld4 + 0) * KSTR + c] = kv.x;
            Kt[(ld4 + 1) * KSTR + c] = kv.y;
            Kt[(ld4 + 2) * KSTR + c] = kv.z;
            Kt[(ld4 + 3) * KSTR + c] = kv.w;
            float4 vv = *(const float4*)(vg + (size_t)(k0 + c) * HSz + ld4);
            *(float4*)&Vs[c * KSTR + ld4] = vv;
        }
        __syncthreads();

        // S = Q @ K^T (already scaled)
        float s[4][4];
        #pragma unroll
        for (int i = 0; i < 4; i++)
            #pragma unroll
            for (int j = 0; j < 4; j++) s[i][j] = 0.f;

        #pragma unroll 8
        for (int kk = 0; kk < 64; kk++) {
            float4 a  = *(const float4*)&Qt[kk * KSTR + ty4];
            float4 bq = *(const float4*)&Kt[kk * KSTR + tx4];
            const float ra[4] = {a.x, a.y, a.z, a.w};
            const float rb[4] = {bq.x, bq.y, bq.z, bq.w};
            #pragma unroll
            for (int i = 0; i < 4; i++)
                #pragma unroll
                for (int j = 0; j < 4; j++)
                    s[i][j] += ra[i] * rb[j];
        }

        // Causal mask: only the diagonal tile needs it (k0 == q0 there)
        if (kt == nkt - 1) {
            #pragma unroll
            for (int i = 0; i < 4; i++)
                #pragma unroll
                for (int j = 0; j < 4; j++)
                    if (tx4 + j > ty4 + i) s[i][j] = -1e30f;
        }

        // Online softmax update
        #pragma unroll
        for (int i = 0; i < 4; i++) {
            float mt = fmaxf(fmaxf(s[i][0], s[i][1]), fmaxf(s[i][2], s[i][3]));
            #pragma unroll
            for (int o = 8; o >= 1; o >>= 1)
                mt = fmaxf(mt, __shfl_xor_sync(0xffffffffu, mt, o));
            const float mnew  = fmaxf(m_i[i], mt);
            const float alpha = __expf(m_i[i] - mnew);
            m_i[i] = mnew;
            float rs = 0.f;
            #pragma unroll
            for (int j = 0; j < 4; j++) {
                const float p = __expf(s[i][j] - mnew);
                s[i][j] = p;
                rs += p;
            }
            #pragma unroll
            for (int o = 8; o >= 1; o >>= 1)
                rs += __shfl_xor_sync(0xffffffffu, rs, o);
            l_i[i] = l_i[i] * alpha + rs;
            #pragma unroll
            for (int j = 0; j < 4; j++) acc[i][j] *= alpha;
        }

        // Stage P transposed: Pt[c][r], float4 along r
        #pragma unroll
        for (int j = 0; j < 4; j++) {
            float4 pv = make_float4(s[0][j], s[1][j], s[2][j], s[3][j]);
            *(float4*)&Pt[(tx4 + j) * KSTR + ty4] = pv;
        }
        __syncthreads();

        // O += P @ V
        #pragma unroll 8
        for (int c = 0; c < 64; c++) {
            float4 rp = *(const float4*)&Pt[c * KSTR + ty4];
            float4 rv = *(const float4*)&Vs[c * KSTR + tx4];
            const float pa[4] = {rp.x, rp.y, rp.z, rp.w};
            const float vb[4] = {rv.x, rv.y, rv.z, rv.w};
            #pragma unroll
            for (int i = 0; i < 4; i++)
                #pragma unroll
                for (int j = 0; j < 4; j++)
                    acc[i][j] += pa[i] * vb[j];
        }
    }

    // Epilogue: normalize + write to [B,S,C] concat-heads buffer
    const int b = bh >> 4;
    const int h = bh & (Hn - 1);
    #pragma unroll
    for (int i = 0; i < 4; i++) {
        const float inv = 1.f / l_i[i];
        const int srow = q0 + ty4 + i;
        float4 o = make_float4(acc[i][0] * inv, acc[i][1] * inv,
                               acc[i][2] * inv, acc[i][3] * inv);
        *(float4*)(g_att + ((size_t)b * Ssz + srow) * Csz + h * HSz + tx4) = o;
    }
}

// ---------------------------------------------------------------------------
// Kernel 3: output projection. out[m,n] = sum_c att[m,c]*Wp[n,c] + bp[n].
// Same SGEMM skeleton; Wp accessed row-major along c (like A).
// ---------------------------------------------------------------------------
__global__ __launch_bounds__(256)
void proj_kernel(const float* __restrict__ Wp,
                 const float* __restrict__ bp,
                 float* __restrict__ out)
{
    __shared__ float As[8][128];
    __shared__ float Bs[8][128];

    const int tid = threadIdx.x;
    const int m0 = blockIdx.y * 128;
    const int n0 = blockIdx.x * 128;

    const int a_row = tid >> 1;
    const int a_k4  = (tid & 1) << 2;
    const float* aptr = g_att + (size_t)(m0 + a_row) * Csz + a_k4;
    const float* bptr = Wp    + (size_t)(n0 + a_row) * Csz + a_k4;

    const int ty4 = (tid >> 4) << 2;
    const int tx4 = (tid & 15) << 2;

    float acc[8][8];
    #pragma unroll
    for (int i = 0; i < 8; i++)
        #pragma unroll
        for (int j = 0; j < 8; j++) acc[i][j] = 0.f;

    for (int k0 = 0; k0 < Csz; k0 += 8) {
        float4 av = *(const float4*)(aptr + k0);
        As[a_k4 + 0][a_row] = av.x;
        As[a_k4 + 1][a_row] = av.y;
        As[a_k4 + 2][a_row] = av.z;
        As[a_k4 + 3][a_row] = av.w;
        float4 bv = *(const float4*)(bptr + k0);
        Bs[a_k4 + 0][a_row] = bv.x;
        Bs[a_k4 + 1][a_row] = bv.y;
        Bs[a_k4 + 2][a_row] = bv.z;
        Bs[a_k4 + 3][a_row] = bv.w;
        __syncthreads();

        #pragma unroll
        for (int kk = 0; kk < 8; kk++) {
            float ra[8], rb[8];
            *(float4*)&ra[0] = *(const float4*)&As[kk][ty4];
            *(float4*)&ra[4] = *(const float4*)&As[kk][64 + ty4];
            *(float4*)&rb[0] = *(const float4*)&Bs[kk][tx4];
            *(float4*)&rb[4] = *(const float4*)&Bs[kk][64 + tx4];
            #pragma unroll
            for (int i = 0; i < 8; i++)
                #pragma unroll
                for (int j = 0; j < 8; j++)
                    acc[i][j] += ra[i] * rb[j];
        }
        __syncthreads();
    }

    #pragma unroll
    for (int cg = 0; cg < 2; cg++) {
        const int n = n0 + cg * 64 + tx4;
        float4 bias = *(const float4*)(bp + n);
        #pragma unroll
        for (int rg = 0; rg < 2; rg++) {
            #pragma unroll
            for (int i = 0; i < 4; i++) {
                const int m = m0 + rg * 64 + ty4 + i;
                float4 o;
                o.x = acc[rg * 4 + i][cg * 4 + 0] + bias.x;
                o.y = acc[rg * 4 + i][cg * 4 + 1] + bias.y;
                o.z = acc[rg * 4 + i][cg * 4 + 2] + bias.z;
                o.w = acc[rg * 4 + i][cg * 4 + 3] + bias.w;
                *(float4*)(out + (size_t)m * Csz + n) = o;
            }
        }
    }
}

// ---------------------------------------------------------------------------
extern "C" void kernel_launch(void* const* d_in, const int* in_sizes, int n_in,
                              void* d_out, int out_size)
{
    const float* x  = (const float*)d_in[0];
    const float* Wq = (const float*)d_in[1];
    const float* Wk = (const float*)d_in[2];
    const float* Wv = (const float*)d_in[3];
    const float* Wp = (const float*)d_in[4];
    const float* bp = (const float*)d_in[5];
    float* out = (float*)d_out;

    const int attn_smem = 4 * 64 * KSTR * (int)sizeof(float);   // 69632 B
    cudaFuncSetAttribute(attn_kernel,
                         cudaFuncAttributeMaxDynamicSharedMemorySize, attn_smem);

    // QKV: M=8192 (24 n-tiles x 64 m-tiles)
    qkv_gemm_kernel<<<dim3(3072 / 128, 8192 / 128), 256>>>(x, Wq, Wk, Wv);
    // Attention: 32 q-tiles x 64 (b,h)
    attn_kernel<<<dim3(Ssz / 64, Bsz * Hn), 256, attn_smem>>>();
    // Projection: N=1024, M=8192
    proj_kernel<<<dim3(Csz / 128, 8192 / 128), 256>>>(Wp, bp, out);
}

// round 14
// speedup vs baseline: 1.4979x; 1.4979x over previous
#include <cuda_runtime.h>
#include <math.h>

// Problem constants
#define Bsz 4
#define Ssz 2048
#define Csz 1024
#define Hn  16
#define HSz 64

// Scratch (allocation-free requirement -> __device__ globals)
__device__ float g_q[Bsz * Hn * Ssz * HSz];   // [B,H,S,HS]
__device__ float g_k[Bsz * Hn * Ssz * HSz];
__device__ float g_v[Bsz * Hn * Ssz * HSz];
__device__ float g_att[Bsz * Ssz * Csz];      // [B,S,C] (heads concatenated)

// ---------------------------------------------------------------------------
// tf32 mma.sync helpers
// ---------------------------------------------------------------------------
__device__ __forceinline__ unsigned f2tf(float f) {
    unsigned r;
    asm("cvt.rna.tf32.f32 %0, %1;" : "=r"(r) : "f"(f));
    return r;
}

__device__ __forceinline__ void mma_tf32(float c[4],
                                         unsigned a0, unsigned a1,
                                         unsigned a2, unsigned a3,
                                         unsigned b0, unsigned b1)
{
    asm volatile(
        "mma.sync.aligned.m16n8k8.row.col.f32.tf32.tf32.f32 "
        "{%0,%1,%2,%3},{%4,%5,%6,%7},{%8,%9},{%0,%1,%2,%3};\n"
        : "+f"(c[0]), "+f"(c[1]), "+f"(c[2]), "+f"(c[3])
        : "r"(a0), "r"(a1), "r"(a2), "r"(a3), "r"(b0), "r"(b1));
}

#define SSTR 136   // smem stride (floats). 136 % 32 == 8 -> frag LDS bank = 8c+g, conflict-free.

// ---------------------------------------------------------------------------
// Kernel 1: fused QKV projection via tf32 tensor cores.
// out[m, n] = sum_c x[m, c] * W[...], n in [0,3072) = (sel, h, d).
// Block tile 128x128x16, 8 warps (2m x 4n), warp tile 64x32 (4x4 m16n8 tiles).
// ---------------------------------------------------------------------------
__global__ __launch_bounds__(256)
void qkv_gemm_kernel(const float* __restrict__ x,
                     const float* __restrict__ Wq,
                     const float* __restrict__ Wk,
                     const float* __restrict__ Wv)
{
    __shared__ float sA[16][SSTR];   // sA[k][m], values already tf32-rounded
    __shared__ float sB[16][SSTR];   // sB[k][n]

    const int tid  = threadIdx.x;
    const int lane = tid & 31;
    const int g    = lane >> 2;      // groupID (0..7)
    const int cc   = lane & 3;       // threadID_in_group (0..3)
    const int wid  = tid >> 5;
    const int wm   = wid & 1;        // warp m (0..1) -> 64 rows
    const int wn   = wid >> 1;       // warp n (0..3) -> 32 cols

    const int m0 = blockIdx.y * 128;
    const int n0 = blockIdx.x * 128;

    // A staging: thread -> row tid/2, k-offset (tid&1)*8, two float4 along k
    const int a_row = tid >> 1;
    const int a_k8  = (tid & 1) << 3;
    const float* aptr = x + (size_t)(m0 + a_row) * Csz + a_k8;

    // B staging: thread -> k row tid/16, n-offset (tid&15)*8, two float4 along n
    const int b_k  = tid >> 4;          // 0..15
    const int b_n8 = (tid & 15) << 3;   // 0..120
    const int nb   = n0 + b_n8;
    const int sel  = nb >> 10;
    const int hh   = (nb >> 6) & (Hn - 1);
    const int dd   = nb & (HSz - 1);
    const float* Wsel = (sel == 0) ? Wq : (sel == 1 ? Wk : Wv);
    const float* wptr = Wsel + (size_t)hh * Csz * HSz + dd;   // + c*HSz

    float acc[4][4][4];
    #pragma unroll
    for (int i = 0; i < 4; i++)
        #pragma unroll
        for (int j = 0; j < 4; j++)
            #pragma unroll
            for (int r = 0; r < 4; r++) acc[i][j][r] = 0.f;

    // Prefetch tile 0
    float4 pa0 = *(const float4*)(aptr);
    float4 pa1 = *(const float4*)(aptr + 4);
    float4 pb0 = *(const float4*)(wptr + (size_t)b_k * HSz);
    float4 pb1 = *(const float4*)(wptr + (size_t)b_k * HSz + 4);

    for (int k0 = 0; k0 < Csz; k0 += 16) {
        // Stage (with tf32 rounding)
        sA[a_k8 + 0][a_row] = __uint_as_float(f2tf(pa0.x));
        sA[a_k8 + 1][a_row] = __uint_as_float(f2tf(pa0.y));
        sA[a_k8 + 2][a_row] = __uint_as_float(f2tf(pa0.z));
        sA[a_k8 + 3][a_row] = __uint_as_float(f2tf(pa0.w));
        sA[a_k8 + 4][a_row] = __uint_as_float(f2tf(pa1.x));
        sA[a_k8 + 5][a_row] = __uint_as_float(f2tf(pa1.y));
        sA[a_k8 + 6][a_row] = __uint_as_float(f2tf(pa1.z));
        sA[a_k8 + 7][a_row] = __uint_as_float(f2tf(pa1.w));
        {
            uint4 t0, t1;
            t0.x = f2tf(pb0.x); t0.y = f2tf(pb0.y); t0.z = f2tf(pb0.z); t0.w = f2tf(pb0.w);
            t1.x = f2tf(pb1.x); t1.y = f2tf(pb1.y); t1.z = f2tf(pb1.z); t1.w = f2tf(pb1.w);
            *(uint4*)&sB[b_k][b_n8]     = t0;
            *(uint4*)&sB[b_k][b_n8 + 4] = t1;
        }
        __syncthreads();

        // Prefetch next tile (issue early; latency hidden by mma)
        if (k0 + 16 < Csz) {
            pa0 = *(const float4*)(aptr + k0 + 16);
            pa1 = *(const float4*)(aptr + k0 + 20);
            pb0 = *(const float4*)(wptr + (size_t)(k0 + 16 + b_k) * HSz);
            pb1 = *(const float4*)(wptr + (size_t)(k0 + 16 + b_k) * HSz + 4);
        }

        // Two k8 steps of mma
        #pragma unroll
        for (int k8 = 0; k8 < 16; k8 += 8) {
            unsigned af[4][4], bf[4][2];
            #pragma unroll
            for (int mt = 0; mt < 4; mt++) {
                const int rb = wm * 64 + mt * 16 + g;
                af[mt][0] = __float_as_uint(sA[k8 + cc    ][rb    ]);
                af[mt][1] = __float_as_uint(sA[k8 + cc    ][rb + 8]);
                af[mt][2] = __float_as_uint(sA[k8 + cc + 4][rb    ]);
                af[mt][3] = __float_as_uint(sA[k8 + cc + 4][rb + 8]);
            }
            #pragma unroll
            for (int nt = 0; nt < 4; nt++) {
                const int nbi = wn * 32 + nt * 8 + g;
                bf[nt][0] = __float_as_uint(sB[k8 + cc    ][nbi]);
                bf[nt][1] = __float_as_uint(sB[k8 + cc + 4][nbi]);
            }
            #pragma unroll
            for (int mt = 0; mt < 4; mt++)
                #pragma unroll
                for (int nt = 0; nt < 4; nt++)
                    mma_tf32(acc[mt][nt], af[mt][0], af[mt][1], af[mt][2], af[mt][3],
                             bf[nt][0], bf[nt][1]);
        }
        __syncthreads();
    }

    // Epilogue: scatter to g_q/g_k/g_v in [B,H,S,HS]
    #pragma unroll
    for (int nt = 0; nt < 4; nt++) {
        const int n  = n0 + wn * 32 + nt * 8 + 2 * cc;
        const int s2 = n >> 10;
        const int h2 = (n >> 6) & (Hn - 1);
        const int d2 = n & (HSz - 1);
        float* obuf = (s2 == 0) ? g_q : (s2 == 1 ? g_k : g_v);
        #pragma unroll
        for (int mt = 0; mt < 4; mt++) {
            const int m  = m0 + wm * 64 + mt * 16 + g;
            const int bb = m >> 11;
            const int ss = m & (Ssz - 1);
            float* base = obuf + (((size_t)(bb * Hn + h2) * Ssz + ss) * HSz + d2);
            *(float2*)base = make_float2(acc[mt][nt][0], acc[mt][nt][1]);
            *(float2*)(base + 8 * HSz) = make_float2(acc[mt][nt][2], acc[mt][nt][3]);
        }
    }
}

// ---------------------------------------------------------------------------
// Kernel 2: flash attention, fp32, causal (unchanged from R13 — verified).
// ---------------------------------------------------------------------------
#define KSTR 68   // smem row stride (floats): 16B-aligned, conflict-reduced

__global__ __launch_bounds__(256)
void attn_kernel()
{
    extern __shared__ float sm[];
    float* Qt = sm;                  // [64][KSTR]  Q transposed (scaled by 1/8)
    float* Kt = Qt + 64 * KSTR;      // [64][KSTR]  K transposed
    float* Vs = Kt + 64 * KSTR;      // [64][KSTR]  V direct
    float* Pt = Vs + 64 * KSTR;      // [64][KSTR]  P transposed

    const int tid = threadIdx.x;
    const int bh  = blockIdx.y;
    const int q0  = blockIdx.x * 64;

    const float* qg = g_q + (size_t)bh * Ssz * HSz;
    const float* kg = g_k + (size_t)bh * Ssz * HSz;
    const float* vg = g_v + (size_t)bh * Ssz * HSz;

    const int lr  = tid >> 4;          // 0..15
    const int ld4 = (tid & 15) << 2;   // 0..60

    #pragma unroll
    for (int it = 0; it < 4; it++) {
        const int r = lr + it * 16;
        float4 qv = *(const float4*)(qg + (size_t)(q0 + r) * HSz + ld4);
        Qt[(ld4 + 0) * KSTR + r] = qv.x * 0.125f;
        Qt[(ld4 + 1) * KSTR + r] = qv.y * 0.125f;
        Qt[(ld4 + 2) * KSTR + r] = qv.z * 0.125f;
        Qt[(ld4 + 3) * KSTR + r] = qv.w * 0.125f;
    }

    const int ty4 = (tid >> 4) << 2;
    const int tx4 = (tid & 15) << 2;

    float m_i[4], l_i[4], acc[4][4];
    #pragma unroll
    for (int i = 0; i < 4; i++) {
        m_i[i] = -1e30f;
        l_i[i] = 0.f;
        #pragma unroll
        for (int j = 0; j < 4; j++) acc[i][j] = 0.f;
    }

    const int nkt = blockIdx.x + 1;
    for (int kt = 0; kt < nkt; kt++) {
        const int k0 = kt * 64;
        __syncthreads();

        #pragma unroll
        for (int it = 0; it < 4; it++) {
            const int c = lr + it * 16;
            float4 kv = *(const float4*)(kg + (size_t)(k0 + c) * HSz + ld4);
            Kt[(ld4 + 0) * KSTR + c] = kv.x;
            Kt[(ld4 + 1) * KSTR + c] = kv.y;
            Kt[(ld4 + 2) * KSTR + c] = kv.z;
            Kt[(ld4 + 3) * KSTR + c] = kv.w;
            float4 vv = *(const float4*)(vg + (size_t)(k0 + c) * HSz + ld4);
            *(float4*)&Vs[c * KSTR + ld4] = vv;
        }
        __syncthreads();

        float s[4][4];
        #pragma unroll
        for (int i = 0; i < 4; i++)
            #pragma unroll
            for (int j = 0; j < 4; j++) s[i][j] = 0.f;

        #pragma unroll 8
        for (int kk = 0; kk < 64; kk++) {
            float4 a  = *(const float4*)&Qt[kk * KSTR + ty4];
            float4 bq = *(const float4*)&Kt[kk * KSTR + tx4];
            const float ra[4] = {a.x, a.y, a.z, a.w};
            const float rb[4] = {bq.x, bq.y, bq.z, bq.w};
            #pragma unroll
            for (int i = 0; i < 4; i++)
                #pragma unroll
                for (int j = 0; j < 4; j++)
                    s[i][j] += ra[i] * rb[j];
        }

        if (kt == nkt - 1) {
            #pragma unroll
            for (int i = 0; i < 4; i++)
                #pragma unroll
                for (int j = 0; j < 4; j++)
                    if (tx4 + j > ty4 + i) s[i][j] = -1e30f;
        }

        #pragma unroll
        for (int i = 0; i < 4; i++) {
            float mt = fmaxf(fmaxf(s[i][0], s[i][1]), fmaxf(s[i][2], s[i][3]));
            #pragma unroll
            for (int o = 8; o >= 1; o >>= 1)
                mt = fmaxf(mt, __shfl_xor_sync(0xffffffffu, mt, o));
            const float mnew  = fmaxf(m_i[i], mt);
            const float alpha = __expf(m_i[i] - mnew);
            m_i[i] = mnew;
            float rs = 0.f;
            #pragma unroll
            for (int j = 0; j < 4; j++) {
                const float p = __expf(s[i][j] - mnew);
                s[i][j] = p;
                rs += p;
            }
            #pragma unroll
            for (int o = 8; o >= 1; o >>= 1)
                rs += __shfl_xor_sync(0xffffffffu, rs, o);
            l_i[i] = l_i[i] * alpha + rs;
            #pragma unroll
            for (int j = 0; j < 4; j++) acc[i][j] *= alpha;
        }

        #pragma unroll
        for (int j = 0; j < 4; j++) {
            float4 pv = make_float4(s[0][j], s[1][j], s[2][j], s[3][j]);
            *(float4*)&Pt[(tx4 + j) * KSTR + ty4] = pv;
        }
        __syncthreads();

        #pragma unroll 8
        for (int c = 0; c < 64; c++) {
            float4 rp = *(const float4*)&Pt[c * KSTR + ty4];
            float4 rv = *(const float4*)&Vs[c * KSTR + tx4];
            const float pa[4] = {rp.x, rp.y, rp.z, rp.w};
            const float vb[4] = {rv.x, rv.y, rv.z, rv.w};
            #pragma unroll
            for (int i = 0; i < 4; i++)
                #pragma unroll
                for (int j = 0; j < 4; j++)
                    acc[i][j] += pa[i] * vb[j];
        }
    }

    const int b = bh >> 4;
    const int h = bh & (Hn - 1);
    #pragma unroll
    for (int i = 0; i < 4; i++) {
        const float inv = 1.f / l_i[i];
        const int srow = q0 + ty4 + i;
        float4 o = make_float4(acc[i][0] * inv, acc[i][1] * inv,
                               acc[i][2] * inv, acc[i][3] * inv);
        *(float4*)(g_att + ((size_t)b * Ssz + srow) * Csz + h * HSz + tx4) = o;
    }
}

// ---------------------------------------------------------------------------
// Kernel 3: output projection via tf32 tensor cores.
// out[m,n] = sum_c att[m,c]*Wp[n,c] + bp[n]. Same skeleton as qkv_gemm;
// both A and B are row-major along k -> both transpose-staged.
// ---------------------------------------------------------------------------
__global__ __launch_bounds__(256)
void proj_kernel(const float* __restrict__ Wp,
                 const float* __restrict__ bp,
                 float* __restrict__ out)
{
    __shared__ float sA[16][SSTR];
    __shared__ float sB[16][SSTR];

    const int tid  = threadIdx.x;
    const int lane = tid & 31;
    const int g    = lane >> 2;
    const int cc   = lane & 3;
    const int wid  = tid >> 5;
    const int wm   = wid & 1;
    const int wn   = wid >> 1;

    const int m0 = blockIdx.y * 128;
    const int n0 = blockIdx.x * 128;

    const int a_row = tid >> 1;
    const int a_k8  = (tid & 1) << 3;
    const float* aptr = g_att + (size_t)(m0 + a_row) * Csz + a_k8;
    const float* bptr = Wp    + (size_t)(n0 + a_row) * Csz + a_k8;

    float acc[4][4][4];
    #pragma unroll
    for (int i = 0; i < 4; i++)
        #pragma unroll
        for (int j = 0; j < 4; j++)
            #pragma unroll
            for (int r = 0; r < 4; r++) acc[i][j][r] = 0.f;

    float4 pa0 = *(const float4*)(aptr);
    float4 pa1 = *(const float4*)(aptr + 4);
    float4 pb0 = *(const float4*)(bptr);
    float4 pb1 = *(const float4*)(bptr + 4);

    for (int k0 = 0; k0 < Csz; k0 += 16) {
        sA[a_k8 + 0][a_row] = __uint_as_float(f2tf(pa0.x));
        sA[a_k8 + 1][a_row] = __uint_as_float(f2tf(pa0.y));
        sA[a_k8 + 2][a_row] = __uint_as_float(f2tf(pa0.z));
        sA[a_k8 + 3][a_row] = __uint_as_float(f2tf(pa0.w));
        sA[a_k8 + 4][a_row] = __uint_as_float(f2tf(pa1.x));
        sA[a_k8 + 5][a_row] = __uint_as_float(f2tf(pa1.y));
        sA[a_k8 + 6][a_row] = __uint_as_float(f2tf(pa1.z));
        sA[a_k8 + 7][a_row] = __uint_as_float(f2tf(pa1.w));
        sB[a_k8 + 0][a_row] = __uint_as_float(f2tf(pb0.x));
        sB[a_k8 + 1][a_row] = __uint_as_float(f2tf(pb0.y));
        sB[a_k8 + 2][a_row] = __uint_as_float(f2tf(pb0.z));
        sB[a_k8 + 3][a_row] = __uint_as_float(f2tf(pb0.w));
        sB[a_k8 + 4][a_row] = __uint_as_float(f2tf(pb1.x));
        sB[a_k8 + 5][a_row] = __uint_as_float(f2tf(pb1.y));
        sB[a_k8 + 6][a_row] = __uint_as_float(f2tf(pb1.z));
        sB[a_k8 + 7][a_row] = __uint_as_float(f2tf(pb1.w));
        __syncthreads();

        if (k0 + 16 < Csz) {
            pa0 = *(const float4*)(aptr + k0 + 16);
            pa1 = *(const float4*)(aptr + k0 + 20);
            pb0 = *(const float4*)(bptr + k0 + 16);
            pb1 = *(const float4*)(bptr + k0 + 20);
        }

        #pragma unroll
        for (int k8 = 0; k8 < 16; k8 += 8) {
            unsigned af[4][4], bf[4][2];
            #pragma unroll
            for (int mt = 0; mt < 4; mt++) {
                const int rb = wm * 64 + mt * 16 + g;
                af[mt][0] = __float_as_uint(sA[k8 + cc    ][rb    ]);
                af[mt][1] = __float_as_uint(sA[k8 + cc    ][rb + 8]);
                af[mt][2] = __float_as_uint(sA[k8 + cc + 4][rb    ]);
                af[mt][3] = __float_as_uint(sA[k8 + cc + 4][rb + 8]);
            }
            #pragma unroll
            for (int nt = 0; nt < 4; nt++) {
                const int nbi = wn * 32 + nt * 8 + g;
                bf[nt][0] = __float_as_uint(sB[k8 + cc    ][nbi]);
                bf[nt][1] = __float_as_uint(sB[k8 + cc + 4][nbi]);
            }
            #pragma unroll
            for (int mt = 0; mt < 4; mt++)
                #pragma unroll
                for (int nt = 0; nt < 4; nt++)
                    mma_tf32(acc[mt][nt], af[mt][0], af[mt][1], af[mt][2], af[mt][3],
                             bf[nt][0], bf[nt][1]);
        }
        __syncthreads();
    }

    #pragma unroll
    for (int nt = 0; nt < 4; nt++) {
        const int n = n0 + wn * 32 + nt * 8 + 2 * cc;
        const float2 bias = *(const float2*)(bp + n);
        #pragma unroll
        for (int mt = 0; mt < 4; mt++) {
            const int m = m0 + wm * 64 + mt * 16 + g;
            float* base = out + (size_t)m * Csz + n;
            *(float2*)base = make_float2(acc[mt][nt][0] + bias.x,
                                         acc[mt][nt][1] + bias.y);
            *(float2*)(base + 8 * Csz) = make_float2(acc[mt][nt][2] + bias.x,
                                                     acc[mt][nt][3] + bias.y);
        }
    }
}

// ---------------------------------------------------------------------------
extern "C" void kernel_launch(void* const* d_in, const int* in_sizes, int n_in,
                              void* d_out, int out_size)
{
    const float* x  = (const float*)d_in[0];
    const float* Wq = (const float*)d_in[1];
    const float* Wk = (const float*)d_in[2];
    const float* Wv = (const float*)d_in[3];
    const float* Wp = (const float*)d_in[4];
    const float* bp = (const float*)d_in[5];
    float* out = (float*)d_out;

    const int attn_smem = 4 * 64 * KSTR * (int)sizeof(float);   // 69632 B
    cudaFuncSetAttribute(attn_kernel,
                         cudaFuncAttributeMaxDynamicSharedMemorySize, attn_smem);

    // QKV: N=3072, M=8192
    qkv_gemm_kernel<<<dim3(3072 / 128, 8192 / 128), 256>>>(x, Wq, Wk, Wv);
    // Attention: 32 q-tiles x 64 (b,h)
    attn_kernel<<<dim3(Ssz / 64, Bsz * Hn), 256, attn_smem>>>();
    // Projection: N=1024, M=8192
    proj_kernel<<<dim3(Csz / 128, 8192 / 128), 256>>>(Wp, bp, out);
}

// round 15
// speedup vs baseline: 2.4624x; 1.6439x over previous
#include <cuda_runtime.h>
#include <math.h>

// Problem constants
#define Bsz 4
#define Ssz 2048
#define Csz 1024
#define Hn  16
#define HSz 64

// Scratch (allocation-free requirement -> __device__ globals)
__device__ float g_q[Bsz * Hn * Ssz * HSz];   // [B,H,S,HS]
__device__ float g_k[Bsz * Hn * Ssz * HSz];
__device__ float g_v[Bsz * Hn * Ssz * HSz];
__device__ float g_att[Bsz * Ssz * Csz];      // [B,S,C] (heads concatenated)

// ---------------------------------------------------------------------------
// tf32 mma.sync helpers
// ---------------------------------------------------------------------------
__device__ __forceinline__ unsigned f2tf(float f) {
    unsigned r;
    asm("cvt.rna.tf32.f32 %0, %1;" : "=r"(r) : "f"(f));
    return r;
}

__device__ __forceinline__ void mma_tf32(float c[4],
                                         unsigned a0, unsigned a1,
                                         unsigned a2, unsigned a3,
                                         unsigned b0, unsigned b1)
{
    asm volatile(
        "mma.sync.aligned.m16n8k8.row.col.f32.tf32.tf32.f32 "
        "{%0,%1,%2,%3},{%4,%5,%6,%7},{%8,%9},{%0,%1,%2,%3};\n"
        : "+f"(c[0]), "+f"(c[1]), "+f"(c[2]), "+f"(c[3])
        : "r"(a0), "r"(a1), "r"(a2), "r"(a3), "r"(b0), "r"(b1));
}

#define SSTR 136   // smem stride (floats). 136 % 32 == 8 -> frag LDS conflict-free.

// ---------------------------------------------------------------------------
// Kernel 1: fused QKV projection, tf32 tensor cores, 2-stage smem pipeline.
// ---------------------------------------------------------------------------
__global__ __launch_bounds__(256)
void qkv_gemm_kernel(const float* __restrict__ x,
                     const float* __restrict__ Wq,
                     const float* __restrict__ Wk,
                     const float* __restrict__ Wv)
{
    __shared__ float sA[2][16][SSTR];   // sA[buf][k][m] (tf32-rounded)
    __shared__ float sB[2][16][SSTR];   // sB[buf][k][n]

    const int tid  = threadIdx.x;
    const int lane = tid & 31;
    const int g    = lane >> 2;
    const int cc   = lane & 3;
    const int wid  = tid >> 5;
    const int wm   = wid & 1;
    const int wn   = wid >> 1;

    const int m0 = blockIdx.y * 128;
    const int n0 = blockIdx.x * 128;

    const int a_row = tid >> 1;
    const int a_k8  = (tid & 1) << 3;
    const float* aptr = x + (size_t)(m0 + a_row) * Csz + a_k8;

    const int b_k  = tid >> 4;          // 0..15
    const int b_n8 = (tid & 15) << 3;   // 0..120
    const int nb   = n0 + b_n8;
    const int sel  = nb >> 10;
    const int hh   = (nb >> 6) & (Hn - 1);
    const int dd   = nb & (HSz - 1);
    const float* Wsel = (sel == 0) ? Wq : (sel == 1 ? Wk : Wv);
    const float* wptr = Wsel + (size_t)hh * Csz * HSz + dd;

    float acc[4][4][4];
    #pragma unroll
    for (int i = 0; i < 4; i++)
        #pragma unroll
        for (int j = 0; j < 4; j++)
            #pragma unroll
            for (int r = 0; r < 4; r++) acc[i][j][r] = 0.f;

    // Preload tile 0 and stage into buffer 0
    float4 pa0 = *(const float4*)(aptr);
    float4 pa1 = *(const float4*)(aptr + 4);
    float4 pb0 = *(const float4*)(wptr + (size_t)b_k * HSz);
    float4 pb1 = *(const float4*)(wptr + (size_t)b_k * HSz + 4);

    sA[0][a_k8 + 0][a_row] = __uint_as_float(f2tf(pa0.x));
    sA[0][a_k8 + 1][a_row] = __uint_as_float(f2tf(pa0.y));
    sA[0][a_k8 + 2][a_row] = __uint_as_float(f2tf(pa0.z));
    sA[0][a_k8 + 3][a_row] = __uint_as_float(f2tf(pa0.w));
    sA[0][a_k8 + 4][a_row] = __uint_as_float(f2tf(pa1.x));
    sA[0][a_k8 + 5][a_row] = __uint_as_float(f2tf(pa1.y));
    sA[0][a_k8 + 6][a_row] = __uint_as_float(f2tf(pa1.z));
    sA[0][a_k8 + 7][a_row] = __uint_as_float(f2tf(pa1.w));
    {
        uint4 t0, t1;
        t0.x = f2tf(pb0.x); t0.y = f2tf(pb0.y); t0.z = f2tf(pb0.z); t0.w = f2tf(pb0.w);
        t1.x = f2tf(pb1.x); t1.y = f2tf(pb1.y); t1.z = f2tf(pb1.z); t1.w = f2tf(pb1.w);
        *(uint4*)&sB[0][b_k][b_n8]     = t0;
        *(uint4*)&sB[0][b_k][b_n8 + 4] = t1;
    }
    __syncthreads();

    for (int k0 = 0; k0 < Csz; k0 += 16) {
        const int p = (k0 >> 4) & 1;
        const bool more = (k0 + 16) < Csz;

        if (more) {  // issue GMEM loads early; latency hides under mma
            pa0 = *(const float4*)(aptr + k0 + 16);
            pa1 = *(const float4*)(aptr + k0 + 20);
            pb0 = *(const float4*)(wptr + (size_t)(k0 + 16 + b_k) * HSz);
            pb1 = *(const float4*)(wptr + (size_t)(k0 + 16 + b_k) * HSz + 4);
        }

        #pragma unroll
        for (int k8 = 0; k8 < 16; k8 += 8) {
            unsigned af[4][4], bf[4][2];
            #pragma unroll
            for (int mt = 0; mt < 4; mt++) {
                const int rb = wm * 64 + mt * 16 + g;
                af[mt][0] = __float_as_uint(sA[p][k8 + cc    ][rb    ]);
                af[mt][1] = __float_as_uint(sA[p][k8 + cc    ][rb + 8]);
                af[mt][2] = __float_as_uint(sA[p][k8 + cc + 4][rb    ]);
                af[mt][3] = __float_as_uint(sA[p][k8 + cc + 4][rb + 8]);
            }
            #pragma unroll
            for (int nt = 0; nt < 4; nt++) {
                const int nbi = wn * 32 + nt * 8 + g;
                bf[nt][0] = __float_as_uint(sB[p][k8 + cc    ][nbi]);
                bf[nt][1] = __float_as_uint(sB[p][k8 + cc + 4][nbi]);
            }
            #pragma unroll
            for (int mt = 0; mt < 4; mt++)
                #pragma unroll
                for (int nt = 0; nt < 4; nt++)
                    mma_tf32(acc[mt][nt], af[mt][0], af[mt][1], af[mt][2], af[mt][3],
                             bf[nt][0], bf[nt][1]);
        }

        if (more) {  // stage next tile into the other buffer (prev readers done)
            const int q = p ^ 1;
            sA[q][a_k8 + 0][a_row] = __uint_as_float(f2tf(pa0.x));
            sA[q][a_k8 + 1][a_row] = __uint_as_float(f2tf(pa0.y));
            sA[q][a_k8 + 2][a_row] = __uint_as_float(f2tf(pa0.z));
            sA[q][a_k8 + 3][a_row] = __uint_as_float(f2tf(pa0.w));
            sA[q][a_k8 + 4][a_row] = __uint_as_float(f2tf(pa1.x));
            sA[q][a_k8 + 5][a_row] = __uint_as_float(f2tf(pa1.y));
            sA[q][a_k8 + 6][a_row] = __uint_as_float(f2tf(pa1.z));
            sA[q][a_k8 + 7][a_row] = __uint_as_float(f2tf(pa1.w));
            uint4 t0, t1;
            t0.x = f2tf(pb0.x); t0.y = f2tf(pb0.y); t0.z = f2tf(pb0.z); t0.w = f2tf(pb0.w);
            t1.x = f2tf(pb1.x); t1.y = f2tf(pb1.y); t1.z = f2tf(pb1.z); t1.w = f2tf(pb1.w);
            *(uint4*)&sB[q][b_k][b_n8]     = t0;
            *(uint4*)&sB[q][b_k][b_n8 + 4] = t1;
        }
        __syncthreads();
    }

    // Epilogue: scatter to g_q/g_k/g_v in [B,H,S,HS]
    #pragma unroll
    for (int nt = 0; nt < 4; nt++) {
        const int n  = n0 + wn * 32 + nt * 8 + 2 * cc;
        const int s2 = n >> 10;
        const int h2 = (n >> 6) & (Hn - 1);
        const int d2 = n & (HSz - 1);
        float* obuf = (s2 == 0) ? g_q : (s2 == 1 ? g_k : g_v);
        #pragma unroll
        for (int mt = 0; mt < 4; mt++) {
            const int m  = m0 + wm * 64 + mt * 16 + g;
            const int bb = m >> 11;
            const int ss = m & (Ssz - 1);
            float* base = obuf + (((size_t)(bb * Hn + h2) * Ssz + ss) * HSz + d2);
            *(float2*)base = make_float2(acc[mt][nt][0], acc[mt][nt][1]);
            *(float2*)(base + 8 * HSz) = make_float2(acc[mt][nt][2], acc[mt][nt][3]);
        }
    }
}

// ---------------------------------------------------------------------------
// Kernel 2: flash attention, tf32 tensor cores, causal.
// 128 queries/block, 64-key tiles. 8 warps, each owns 16 query rows
// (softmax reductions stay within the 4-lane mma quad -> shfl_xor 1,2).
// ---------------------------------------------------------------------------
#define QT 128
#define KT 64
#define PSTR 136   // sQ/sP stride (%32==8 -> conflict-free frag LDS)
#define VSTR 72    // sK/sV stride (%32==8)

__global__ __launch_bounds__(256)
void attn_kernel()
{
    extern __shared__ float smem[];
    float* sQ = smem;                  // [HSz][PSTR]  Q^T, tf32, pre-scaled
    float* sP = sQ + HSz * PSTR;       // [KT][PSTR]   P^T, tf32
    float* sK = sP + KT * PSTR;        // [HSz][VSTR]  K^T, tf32
    float* sV = sK + HSz * VSTR;       // [KT][VSTR]   V,   tf32

    const int tid  = threadIdx.x;
    const int lane = tid & 31;
    const int g    = lane >> 2;
    const int cc   = lane & 3;
    const int wid  = tid >> 5;
    const int bh   = blockIdx.y;
    const int qt   = (int)gridDim.x - 1 - (int)blockIdx.x;  // heavy tiles first
    const int q0   = qt * QT;

    const float* qg = g_q + (size_t)bh * Ssz * HSz;
    const float* kg = g_k + (size_t)bh * Ssz * HSz;
    const float* vg = g_v + (size_t)bh * Ssz * HSz;

    // Load Q transposed (lanes walk rows -> conflict-free transpose stores)
    #pragma unroll
    for (int it = 0; it < 8; it++) {
        const int idx = tid + it * 256;
        const int r   = idx & 127;
        const int d4  = (idx >> 7) << 2;
        float4 qv = *(const float4*)(qg + (size_t)(q0 + r) * HSz + d4);
        sQ[(d4 + 0) * PSTR + r] = __uint_as_float(f2tf(qv.x * 0.125f));
        sQ[(d4 + 1) * PSTR + r] = __uint_as_float(f2tf(qv.y * 0.125f));
        sQ[(d4 + 2) * PSTR + r] = __uint_as_float(f2tf(qv.z * 0.125f));
        sQ[(d4 + 3) * PSTR + r] = __uint_as_float(f2tf(qv.w * 0.125f));
    }

    float o[8][4];
    float m_i[2], l_i[2];
    #pragma unroll
    for (int nt = 0; nt < 8; nt++)
        #pragma unroll
        for (int j = 0; j < 4; j++) o[nt][j] = 0.f;
    m_i[0] = m_i[1] = -1e30f;
    l_i[0] = l_i[1] = 0.f;

    const int rb  = wid * 16 + g;     // warp's query row (g half)
    const int nkt = 2 * qt + 2;

    for (int kt = 0; kt < nkt; kt++) {
        const int k0 = kt * KT;
        __syncthreads();   // prior P@V done reading sV before overwrite

        // K transposed (lanes walk rows -> conflict-free stores)
        #pragma unroll
        for (int it = 0; it < 4; it++) {
            const int idx = tid + it * 256;
            const int r   = idx & 63;
            const int d4  = (idx >> 6) << 2;
            float4 kv = *(const float4*)(kg + (size_t)(k0 + r) * HSz + d4);
            sK[(d4 + 0) * VSTR + r] = __uint_as_float(f2tf(kv.x));
            sK[(d4 + 1) * VSTR + r] = __uint_as_float(f2tf(kv.y));
            sK[(d4 + 2) * VSTR + r] = __uint_as_float(f2tf(kv.z));
            sK[(d4 + 3) * VSTR + r] = __uint_as_float(f2tf(kv.w));
        }
        // V direct (coalesced load + vector store)
        #pragma unroll
        for (int it = 0; it < 4; it++) {
            const int idx = tid + it * 256;
            const int r   = idx >> 4;
            const int d4  = (idx & 15) << 2;
            float4 vv = *(const float4*)(vg + (size_t)(k0 + r) * HSz + d4);
            uint4 t;
            t.x = f2tf(vv.x); t.y = f2tf(vv.y); t.z = f2tf(vv.z); t.w = f2tf(vv.w);
            *(uint4*)&sV[r * VSTR + d4] = t;
        }
        __syncthreads();

        // S = (Q/8) @ K^T via mma
        float s[8][4];
        #pragma unroll
        for (int nt = 0; nt < 8; nt++)
            #pragma unroll
            for (int j = 0; j < 4; j++) s[nt][j] = 0.f;

        #pragma unroll
        for (int k8 = 0; k8 < HSz; k8 += 8) {
            const unsigned a0 = __float_as_uint(sQ[(k8 + cc    ) * PSTR + rb    ]);
            const unsigned a1 = __float_as_uint(sQ[(k8 + cc    ) * PSTR + rb + 8]);
            const unsigned a2 = __float_as_uint(sQ[(k8 + cc + 4) * PSTR + rb    ]);
            const unsigned a3 = __float_as_uint(sQ[(k8 + cc + 4) * PSTR + rb + 8]);
            #pragma unroll
            for (int nt = 0; nt < 8; nt++) {
                const unsigned b0 = __float_as_uint(sK[(k8 + cc    ) * VSTR + nt * 8 + g]);
                const unsigned b1 = __float_as_uint(sK[(k8 + cc + 4) * VSTR + nt * 8 + g]);
                mma_tf32(s[nt], a0, a1, a2, a3, b0, b1);
            }
        }

        // Causal mask (skip for warps fully below this key tile)
        if (k0 + KT - 1 > q0 + wid * 16) {
            const int r0 = q0 + rb;
            #pragma unroll
            for (int nt = 0; nt < 8; nt++) {
                const int c0 = k0 + nt * 8 + 2 * cc;
                if (c0     > r0    ) s[nt][0] = -1e30f;
                if (c0 + 1 > r0    ) s[nt][1] = -1e30f;
                if (c0     > r0 + 8) s[nt][2] = -1e30f;
                if (c0 + 1 > r0 + 8) s[nt][3] = -1e30f;
            }
        }

        // Online softmax (rows g and g+8; reduce across the 4-lane quad)
        #pragma unroll
        for (int hr = 0; hr < 2; hr++) {
            float mt = -1e30f;
            #pragma unroll
            for (int nt = 0; nt < 8; nt++)
                mt = fmaxf(mt, fmaxf(s[nt][hr * 2], s[nt][hr * 2 + 1]));
            mt = fmaxf(mt, __shfl_xor_sync(0xffffffffu, mt, 1));
            mt = fmaxf(mt, __shfl_xor_sync(0xffffffffu, mt, 2));
            const float mnew  = fmaxf(m_i[hr], mt);
            const float alpha = __expf(m_i[hr] - mnew);
            m_i[hr] = mnew;
            float rs = 0.f;
            #pragma unroll
            for (int nt = 0; nt < 8; nt++) {
                const float p0 = __expf(s[nt][hr * 2]     - mnew);
                const float p1 = __expf(s[nt][hr * 2 + 1] - mnew);
                s[nt][hr * 2]     = p0;
                s[nt][hr * 2 + 1] = p1;
                rs += p0 + p1;
            }
            rs += __shfl_xor_sync(0xffffffffu, rs, 1);
            rs += __shfl_xor_sync(0xffffffffu, rs, 2);
            l_i[hr] = l_i[hr] * alpha + rs;
            #pragma unroll
            for (int nt = 0; nt < 8; nt++) {
                o[nt][hr * 2]     *= alpha;
                o[nt][hr * 2 + 1] *= alpha;
            }
        }

        // Stage P^T (each warp writes & reads only its own 16 columns)
        #pragma unroll
        for (int nt = 0; nt < 8; nt++) {
            const int c0 = nt * 8 + 2 * cc;
            sP[(c0    ) * PSTR + rb    ] = __uint_as_float(f2tf(s[nt][0]));
            sP[(c0 + 1) * PSTR + rb    ] = __uint_as_float(f2tf(s[nt][1]));
            sP[(c0    ) * PSTR + rb + 8] = __uint_as_float(f2tf(s[nt][2]));
            sP[(c0 + 1) * PSTR + rb + 8] = __uint_as_float(f2tf(s[nt][3]));
        }
        __syncwarp();

        // O += P @ V via mma
        #pragma unroll
        for (int k8 = 0; k8 < KT; k8 += 8) {
            const unsigned a0 = __float_as_uint(sP[(k8 + cc    ) * PSTR + rb    ]);
            const unsigned a1 = __float_as_uint(sP[(k8 + cc    ) * PSTR + rb + 8]);
            const unsigned a2 = __float_as_uint(sP[(k8 + cc + 4) * PSTR + rb    ]);
            const unsigned a3 = __float_as_uint(sP[(k8 + cc + 4) * PSTR + rb + 8]);
            #pragma unroll
            for (int nt = 0; nt < 8; nt++) {
                const unsigned b0 = __float_as_uint(sV[(k8 + cc    ) * VSTR + nt * 8 + g]);
                const unsigned b1 = __float_as_uint(sV[(k8 + cc + 4) * VSTR + nt * 8 + g]);
                mma_tf32(o[nt], a0, a1, a2, a3, b0, b1);
            }
        }
    }

    // Epilogue: normalize + write concat-heads [B,S,C]
    const int b = bh >> 4;
    const int h = bh & (Hn - 1);
    #pragma unroll
    for (int hr = 0; hr < 2; hr++) {
        const float inv = 1.f / l_i[hr];
        const int row = q0 + rb + hr * 8;
        #pragma unroll
        for (int nt = 0; nt < 8; nt++) {
            float2 ov = make_float2(o[nt][hr * 2] * inv, o[nt][hr * 2 + 1] * inv);
            *(float2*)(g_att + ((size_t)b * Ssz + row) * Csz
                       + h * HSz + nt * 8 + 2 * cc) = ov;
        }
    }
}

// ---------------------------------------------------------------------------
// Kernel 3: output projection, tf32 tensor cores, 2-stage smem pipeline.
// ---------------------------------------------------------------------------
__global__ __launch_bounds__(256)
void proj_kernel(const float* __restrict__ Wp,
                 const float* __restrict__ bp,
                 float* __restrict__ out)
{
    __shared__ float sA[2][16][SSTR];
    __shared__ float sB[2][16][SSTR];

    const int tid  = threadIdx.x;
    const int lane = tid & 31;
    const int g    = lane >> 2;
    const int cc   = lane & 3;
    const int wid  = tid >> 5;
    const int wm   = wid & 1;
    const int wn   = wid >> 1;

    const int m0 = blockIdx.y * 128;
    const int n0 = blockIdx.x * 128;

    const int a_row = tid >> 1;
    const int a_k8  = (tid & 1) << 3;
    const float* aptr = g_att + (size_t)(m0 + a_row) * Csz + a_k8;
    const float* bptr = Wp    + (size_t)(n0 + a_row) * Csz + a_k8;

    float acc[4][4][4];
    #pragma unroll
    for (int i = 0; i < 4; i++)
        #pragma unroll
        for (int j = 0; j < 4; j++)
            #pragma unroll
            for (int r = 0; r < 4; r++) acc[i][j][r] = 0.f;

    float4 pa0 = *(const float4*)(aptr);
    float4 pa1 = *(const float4*)(aptr + 4);
    float4 pb0 = *(const float4*)(bptr);
    float4 pb1 = *(const float4*)(bptr + 4);

    sA[0][a_k8 + 0][a_row] = __uint_as_float(f2tf(pa0.x));
    sA[0][a_k8 + 1][a_row] = __uint_as_float(f2tf(pa0.y));
    sA[0][a_k8 + 2][a_row] = __uint_as_float(f2tf(pa0.z));
    sA[0][a_k8 + 3][a_row] = __uint_as_float(f2tf(pa0.w));
    sA[0][a_k8 + 4][a_row] = __uint_as_float(f2tf(pa1.x));
    sA[0][a_k8 + 5][a_row] = __uint_as_float(f2tf(pa1.y));
    sA[0][a_k8 + 6][a_row] = __uint_as_float(f2tf(pa1.z));
    sA[0][a_k8 + 7][a_row] = __uint_as_float(f2tf(pa1.w));
    sB[0][a_k8 + 0][a_row] = __uint_as_float(f2tf(pb0.x));
    sB[0][a_k8 + 1][a_row] = __uint_as_float(f2tf(pb0.y));
    sB[0][a_k8 + 2][a_row] = __uint_as_float(f2tf(pb0.z));
    sB[0][a_k8 + 3][a_row] = __uint_as_float(f2tf(pb0.w));
    sB[0][a_k8 + 4][a_row] = __uint_as_float(f2tf(pb1.x));
    sB[0][a_k8 + 5][a_row] = __uint_as_float(f2tf(pb1.y));
    sB[0][a_k8 + 6][a_row] = __uint_as_float(f2tf(pb1.z));
    sB[0][a_k8 + 7][a_row] = __uint_as_float(f2tf(pb1.w));
    __syncthreads();

    for (int k0 = 0; k0 < Csz; k0 += 16) {
        const int p = (k0 >> 4) & 1;
        const bool more = (k0 + 16) < Csz;

        if (more) {
            pa0 = *(const float4*)(aptr + k0 + 16);
            pa1 = *(const float4*)(aptr + k0 + 20);
            pb0 = *(const float4*)(bptr + k0 + 16);
            pb1 = *(const float4*)(bptr + k0 + 20);
        }

        #pragma unroll
        for (int k8 = 0; k8 < 16; k8 += 8) {
            unsigned af[4][4], bf[4][2];
            #pragma unroll
            for (int mt = 0; mt < 4; mt++) {
                const int rbm = wm * 64 + mt * 16 + g;
                af[mt][0] = __float_as_uint(sA[p][k8 + cc    ][rbm    ]);
                af[mt][1] = __float_as_uint(sA[p][k8 + cc    ][rbm + 8]);
                af[mt][2] = __float_as_uint(sA[p][k8 + cc + 4][rbm    ]);
                af[mt][3] = __float_as_uint(sA[p][k8 + cc + 4][rbm + 8]);
            }
            #pragma unroll
            for (int nt = 0; nt < 4; nt++) {
                const int nbi = wn * 32 + nt * 8 + g;
                bf[nt][0] = __float_as_uint(sB[p][k8 + cc    ][nbi]);
                bf[nt][1] = __float_as_uint(sB[p][k8 + cc + 4][nbi]);
            }
            #pragma unroll
            for (int mt = 0; mt < 4; mt++)
                #pragma unroll
                for (int nt = 0; nt < 4; nt++)
                    mma_tf32(acc[mt][nt], af[mt][0], af[mt][1], af[mt][2], af[mt][3],
                             bf[nt][0], bf[nt][1]);
        }

        if (more) {
            const int q = p ^ 1;
            sA[q][a_k8 + 0][a_row] = __uint_as_float(f2tf(pa0.x));
            sA[q][a_k8 + 1][a_row] = __uint_as_float(f2tf(pa0.y));
            sA[q][a_k8 + 2][a_row] = __uint_as_float(f2tf(pa0.z));
            sA[q][a_k8 + 3][a_row] = __uint_as_float(f2tf(pa0.w));
            sA[q][a_k8 + 4][a_row] = __uint_as_float(f2tf(pa1.x));
            sA[q][a_k8 + 5][a_row] = __uint_as_float(f2tf(pa1.y));
            sA[q][a_k8 + 6][a_row] = __uint_as_float(f2tf(pa1.z));
            sA[q][a_k8 + 7][a_row] = __uint_as_float(f2tf(pa1.w));
            sB[q][a_k8 + 0][a_row] = __uint_as_float(f2tf(pb0.x));
            sB[q][a_k8 + 1][a_row] = __uint_as_float(f2tf(pb0.y));
            sB[q][a_k8 + 2][a_row] = __uint_as_float(f2tf(pb0.z));
            sB[q][a_k8 + 3][a_row] = __uint_as_float(f2tf(pb0.w));
            sB[q][a_k8 + 4][a_row] = __uint_as_float(f2tf(pb1.x));
            sB[q][a_k8 + 5][a_row] = __uint_as_float(f2tf(pb1.y));
            sB[q][a_k8 + 6][a_row] = __uint_as_float(f2tf(pb1.z));
            sB[q][a_k8 + 7][a_row] = __uint_as_float(f2tf(pb1.w));
        }
        __syncthreads();
    }

    #pragma unroll
    for (int nt = 0; nt < 4; nt++) {
        const int n = n0 + wn * 32 + nt * 8 + 2 * cc;
        const float2 bias = *(const float2*)(bp + n);
        #pragma unroll
        for (int mt = 0; mt < 4; mt++) {
            const int m = m0 + wm * 64 + mt * 16 + g;
            float* base = out + (size_t)m * Csz + n;
            *(float2*)base = make_float2(acc[mt][nt][0] + bias.x,
                                         acc[mt][nt][1] + bias.y);
            *(float2*)(base + 8 * Csz) = make_float2(acc[mt][nt][2] + bias.x,
                                                     acc[mt][nt][3] + bias.y);
        }
    }
}

// ---------------------------------------------------------------------------
extern "C" void kernel_launch(void* const* d_in, const int* in_sizes, int n_in,
                              void* d_out, int out_size)
{
    const float* x  = (const float*)d_in[0];
    const float* Wq = (const float*)d_in[1];
    const float* Wk = (const float*)d_in[2];
    const float* Wv = (const float*)d_in[3];
    const float* Wp = (const float*)d_in[4];
    const float* bp = (const float*)d_in[5];
    float* out = (float*)d_out;

    const int attn_smem = (HSz * PSTR + KT * PSTR + HSz * VSTR + KT * VSTR)
                          * (int)sizeof(float);   // 106496 B
    cudaFuncSetAttribute(attn_kernel,
                         cudaFuncAttributeMaxDynamicSharedMemorySize, attn_smem);

    // QKV: N=3072, M=8192
    qkv_gemm_kernel<<<dim3(3072 / 128, 8192 / 128), 256>>>(x, Wq, Wk, Wv);
    // Attention: 16 q-tiles (128 rows each) x 64 (b,h)
    attn_kernel<<<dim3(Ssz / QT, Bsz * Hn), 256, attn_smem>>>();
    // Projection: N=1024, M=8192
    proj_kernel<<<dim3(Csz / 128, 8192 / 128), 256>>>(Wp, bp, out);
}

// round 16
// speedup vs baseline: 2.4798x; 1.0071x over previous
#include <cuda_runtime.h>
#include <math.h>

// Problem constants
#define Bsz 4
#define Ssz 2048
#define Csz 1024
#define Hn  16
#define HSz 64

// Scratch (allocation-free requirement -> __device__ globals)
__device__ float g_q[Bsz * Hn * Ssz * HSz];   // [B,H,S,HS]
__device__ float g_k[Bsz * Hn * Ssz * HSz];
__device__ float g_v[Bsz * Hn * Ssz * HSz];
__device__ float g_att[Bsz * Ssz * Csz];      // [B,S,C] (heads concatenated)

// ---------------------------------------------------------------------------
// tf32 mma.sync helpers
// ---------------------------------------------------------------------------
__device__ __forceinline__ unsigned f2tf(float f) {
    unsigned r;
    asm("cvt.rna.tf32.f32 %0, %1;" : "=r"(r) : "f"(f));
    return r;
}

__device__ __forceinline__ void mma_tf32(float c[4],
                                         unsigned a0, unsigned a1,
                                         unsigned a2, unsigned a3,
                                         unsigned b0, unsigned b1)
{
    asm volatile(
        "mma.sync.aligned.m16n8k8.row.col.f32.tf32.tf32.f32 "
        "{%0,%1,%2,%3},{%4,%5,%6,%7},{%8,%9},{%0,%1,%2,%3};\n"
        : "+f"(c[0]), "+f"(c[1]), "+f"(c[2]), "+f"(c[3])
        : "r"(a0), "r"(a1), "r"(a2), "r"(a3), "r"(b0), "r"(b1));
}

#define SSTR 136   // smem stride (floats). 136 % 32 == 8 -> frag LDS conflict-free.

// ---------------------------------------------------------------------------
// Kernel 1: fused QKV projection, tf32 tensor cores, 2-stage smem pipeline.
// ---------------------------------------------------------------------------
__global__ __launch_bounds__(256)
void qkv_gemm_kernel(const float* __restrict__ x,
                     const float* __restrict__ Wq,
                     const float* __restrict__ Wk,
                     const float* __restrict__ Wv)
{
    __shared__ float sA[2][16][SSTR];   // sA[buf][k][m] (tf32-rounded)
    __shared__ float sB[2][16][SSTR];   // sB[buf][k][n]

    const int tid  = threadIdx.x;
    const int lane = tid & 31;
    const int g    = lane >> 2;
    const int cc   = lane & 3;
    const int wid  = tid >> 5;
    const int wm   = wid & 1;
    const int wn   = wid >> 1;

    const int m0 = blockIdx.y * 128;
    const int n0 = blockIdx.x * 128;

    const int a_row = tid >> 1;
    const int a_k8  = (tid & 1) << 3;
    const float* aptr = x + (size_t)(m0 + a_row) * Csz + a_k8;

    const int b_k  = tid >> 4;          // 0..15
    const int b_n8 = (tid & 15) << 3;   // 0..120
    const int nb   = n0 + b_n8;
    const int sel  = nb >> 10;
    const int hh   = (nb >> 6) & (Hn - 1);
    const int dd   = nb & (HSz - 1);
    const float* Wsel = (sel == 0) ? Wq : (sel == 1 ? Wk : Wv);
    const float* wptr = Wsel + (size_t)hh * Csz * HSz + dd;

    float acc[4][4][4];
    #pragma unroll
    for (int i = 0; i < 4; i++)
        #pragma unroll
        for (int j = 0; j < 4; j++)
            #pragma unroll
            for (int r = 0; r < 4; r++) acc[i][j][r] = 0.f;

    // Preload tile 0 and stage into buffer 0
    float4 pa0 = *(const float4*)(aptr);
    float4 pa1 = *(const float4*)(aptr + 4);
    float4 pb0 = *(const float4*)(wptr + (size_t)b_k * HSz);
    float4 pb1 = *(const float4*)(wptr + (size_t)b_k * HSz + 4);

    sA[0][a_k8 + 0][a_row] = __uint_as_float(f2tf(pa0.x));
    sA[0][a_k8 + 1][a_row] = __uint_as_float(f2tf(pa0.y));
    sA[0][a_k8 + 2][a_row] = __uint_as_float(f2tf(pa0.z));
    sA[0][a_k8 + 3][a_row] = __uint_as_float(f2tf(pa0.w));
    sA[0][a_k8 + 4][a_row] = __uint_as_float(f2tf(pa1.x));
    sA[0][a_k8 + 5][a_row] = __uint_as_float(f2tf(pa1.y));
    sA[0][a_k8 + 6][a_row] = __uint_as_float(f2tf(pa1.z));
    sA[0][a_k8 + 7][a_row] = __uint_as_float(f2tf(pa1.w));
    {
        uint4 t0, t1;
        t0.x = f2tf(pb0.x); t0.y = f2tf(pb0.y); t0.z = f2tf(pb0.z); t0.w = f2tf(pb0.w);
        t1.x = f2tf(pb1.x); t1.y = f2tf(pb1.y); t1.z = f2tf(pb1.z); t1.w = f2tf(pb1.w);
        *(uint4*)&sB[0][b_k][b_n8]     = t0;
        *(uint4*)&sB[0][b_k][b_n8 + 4] = t1;
    }
    __syncthreads();

    for (int k0 = 0; k0 < Csz; k0 += 16) {
        const int p = (k0 >> 4) & 1;
        const bool more = (k0 + 16) < Csz;

        if (more) {  // issue GMEM loads early; latency hides under mma
            pa0 = *(const float4*)(aptr + k0 + 16);
            pa1 = *(const float4*)(aptr + k0 + 20);
            pb0 = *(const float4*)(wptr + (size_t)(k0 + 16 + b_k) * HSz);
            pb1 = *(const float4*)(wptr + (size_t)(k0 + 16 + b_k) * HSz + 4);
        }

        #pragma unroll
        for (int k8 = 0; k8 < 16; k8 += 8) {
            unsigned af[4][4], bf[4][2];
            #pragma unroll
            for (int mt = 0; mt < 4; mt++) {
                const int rb = wm * 64 + mt * 16 + g;
                af[mt][0] = __float_as_uint(sA[p][k8 + cc    ][rb    ]);
                af[mt][1] = __float_as_uint(sA[p][k8 + cc    ][rb + 8]);
                af[mt][2] = __float_as_uint(sA[p][k8 + cc + 4][rb    ]);
                af[mt][3] = __float_as_uint(sA[p][k8 + cc + 4][rb + 8]);
            }
            #pragma unroll
            for (int nt = 0; nt < 4; nt++) {
                const int nbi = wn * 32 + nt * 8 + g;
                bf[nt][0] = __float_as_uint(sB[p][k8 + cc    ][nbi]);
                bf[nt][1] = __float_as_uint(sB[p][k8 + cc + 4][nbi]);
            }
            #pragma unroll
            for (int mt = 0; mt < 4; mt++)
                #pragma unroll
                for (int nt = 0; nt < 4; nt++)
                    mma_tf32(acc[mt][nt], af[mt][0], af[mt][1], af[mt][2], af[mt][3],
                             bf[nt][0], bf[nt][1]);
        }

        if (more) {  // stage next tile into the other buffer (prev readers done)
            const int q = p ^ 1;
            sA[q][a_k8 + 0][a_row] = __uint_as_float(f2tf(pa0.x));
            sA[q][a_k8 + 1][a_row] = __uint_as_float(f2tf(pa0.y));
            sA[q][a_k8 + 2][a_row] = __uint_as_float(f2tf(pa0.z));
            sA[q][a_k8 + 3][a_row] = __uint_as_float(f2tf(pa0.w));
            sA[q][a_k8 + 4][a_row] = __uint_as_float(f2tf(pa1.x));
            sA[q][a_k8 + 5][a_row] = __uint_as_float(f2tf(pa1.y));
            sA[q][a_k8 + 6][a_row] = __uint_as_float(f2tf(pa1.z));
            sA[q][a_k8 + 7][a_row] = __uint_as_float(f2tf(pa1.w));
            uint4 t0, t1;
            t0.x = f2tf(pb0.x); t0.y = f2tf(pb0.y); t0.z = f2tf(pb0.z); t0.w = f2tf(pb0.w);
            t1.x = f2tf(pb1.x); t1.y = f2tf(pb1.y); t1.z = f2tf(pb1.z); t1.w = f2tf(pb1.w);
            *(uint4*)&sB[q][b_k][b_n8]     = t0;
            *(uint4*)&sB[q][b_k][b_n8 + 4] = t1;
        }
        __syncthreads();
    }

    // Epilogue: scatter to g_q/g_k/g_v in [B,H,S,HS]
    #pragma unroll
    for (int nt = 0; nt < 4; nt++) {
        const int n  = n0 + wn * 32 + nt * 8 + 2 * cc;
        const int s2 = n >> 10;
        const int h2 = (n >> 6) & (Hn - 1);
        const int d2 = n & (HSz - 1);
        float* obuf = (s2 == 0) ? g_q : (s2 == 1 ? g_k : g_v);
        #pragma unroll
        for (int mt = 0; mt < 4; mt++) {
            const int m  = m0 + wm * 64 + mt * 16 + g;
            const int bb = m >> 11;
            const int ss = m & (Ssz - 1);
            float* base = obuf + (((size_t)(bb * Hn + h2) * Ssz + ss) * HSz + d2);
            *(float2*)base = make_float2(acc[mt][nt][0], acc[mt][nt][1]);
            *(float2*)(base + 8 * HSz) = make_float2(acc[mt][nt][2], acc[mt][nt][3]);
        }
    }
}

// ---------------------------------------------------------------------------
// Kernel 2: flash attention, tf32 tensor cores, causal.
// 128 queries/block, 64-key tiles. 8 warps, each owns 16 query rows
// (softmax reductions stay within the 4-lane mma quad -> shfl_xor 1,2).
// ---------------------------------------------------------------------------
#define QT 128
#define KT 64
#define PSTR 136   // sQ/sP stride (%32==8 -> conflict-free frag LDS)
#define VSTR 72    // sK/sV stride (%32==8)

__global__ __launch_bounds__(256)
void attn_kernel()
{
    extern __shared__ float smem[];
    float* sQ = smem;                  // [HSz][PSTR]  Q^T, tf32, pre-scaled
    float* sP = sQ + HSz * PSTR;       // [KT][PSTR]   P^T, tf32
    float* sK = sP + KT * PSTR;        // [HSz][VSTR]  K^T, tf32
    float* sV = sK + HSz * VSTR;       // [KT][VSTR]   V,   tf32

    const int tid  = threadIdx.x;
    const int lane = tid & 31;
    const int g    = lane >> 2;
    const int cc   = lane & 3;
    const int wid  = tid >> 5;
    const int bh   = blockIdx.y;
    const int qt   = (int)gridDim.x - 1 - (int)blockIdx.x;  // heavy tiles first
    const int q0   = qt * QT;

    const float* qg = g_q + (size_t)bh * Ssz * HSz;
    const float* kg = g_k + (size_t)bh * Ssz * HSz;
    const float* vg = g_v + (size_t)bh * Ssz * HSz;

    // Load Q transposed (lanes walk rows -> conflict-free transpose stores)
    #pragma unroll
    for (int it = 0; it < 8; it++) {
        const int idx = tid + it * 256;
        const int r   = idx & 127;
        const int d4  = (idx >> 7) << 2;
        float4 qv = *(const float4*)(qg + (size_t)(q0 + r) * HSz + d4);
        sQ[(d4 + 0) * PSTR + r] = __uint_as_float(f2tf(qv.x * 0.125f));
        sQ[(d4 + 1) * PSTR + r] = __uint_as_float(f2tf(qv.y * 0.125f));
        sQ[(d4 + 2) * PSTR + r] = __uint_as_float(f2tf(qv.z * 0.125f));
        sQ[(d4 + 3) * PSTR + r] = __uint_as_float(f2tf(qv.w * 0.125f));
    }

    float o[8][4];
    float m_i[2], l_i[2];
    #pragma unroll
    for (int nt = 0; nt < 8; nt++)
        #pragma unroll
        for (int j = 0; j < 4; j++) o[nt][j] = 0.f;
    m_i[0] = m_i[1] = -1e30f;
    l_i[0] = l_i[1] = 0.f;

    const int rb  = wid * 16 + g;     // warp's query row (g half)
    const int nkt = 2 * qt + 2;

    for (int kt = 0; kt < nkt; kt++) {
        const int k0 = kt * KT;
        __syncthreads();   // prior P@V done reading sV before overwrite

        // K transposed (lanes walk rows -> conflict-free stores)
        #pragma unroll
        for (int it = 0; it < 4; it++) {
            const int idx = tid + it * 256;
            const int r   = idx & 63;
            const int d4  = (idx >> 6) << 2;
            float4 kv = *(const float4*)(kg + (size_t)(k0 + r) * HSz + d4);
            sK[(d4 + 0) * VSTR + r] = __uint_as_float(f2tf(kv.x));
            sK[(d4 + 1) * VSTR + r] = __uint_as_float(f2tf(kv.y));
            sK[(d4 + 2) * VSTR + r] = __uint_as_float(f2tf(kv.z));
            sK[(d4 + 3) * VSTR + r] = __uint_as_float(f2tf(kv.w));
        }
        // V direct (coalesced load + vector store)
        #pragma unroll
        for (int it = 0; it < 4; it++) {
            const int idx = tid + it * 256;
            const int r   = idx >> 4;
            const int d4  = (idx & 15) << 2;
            float4 vv = *(const float4*)(vg + (size_t)(k0 + r) * HSz + d4);
            uint4 t;
            t.x = f2tf(vv.x); t.y = f2tf(vv.y); t.z = f2tf(vv.z); t.w = f2tf(vv.w);
            *(uint4*)&sV[r * VSTR + d4] = t;
        }
        __syncthreads();

        // S = (Q/8) @ K^T via mma
        float s[8][4];
        #pragma unroll
        for (int nt = 0; nt < 8; nt++)
            #pragma unroll
            for (int j = 0; j < 4; j++) s[nt][j] = 0.f;

        #pragma unroll
        for (int k8 = 0; k8 < HSz; k8 += 8) {
            const unsigned a0 = __float_as_uint(sQ[(k8 + cc    ) * PSTR + rb    ]);
            const unsigned a1 = __float_as_uint(sQ[(k8 + cc    ) * PSTR + rb + 8]);
            const unsigned a2 = __float_as_uint(sQ[(k8 + cc + 4) * PSTR + rb    ]);
            const unsigned a3 = __float_as_uint(sQ[(k8 + cc + 4) * PSTR + rb + 8]);
            #pragma unroll
            for (int nt = 0; nt < 8; nt++) {
                const unsigned b0 = __float_as_uint(sK[(k8 + cc    ) * VSTR + nt * 8 + g]);
                const unsigned b1 = __float_as_uint(sK[(k8 + cc + 4) * VSTR + nt * 8 + g]);
                mma_tf32(s[nt], a0, a1, a2, a3, b0, b1);
            }
        }

        // Causal mask (skip for warps fully below this key tile)
        if (k0 + KT - 1 > q0 + wid * 16) {
            const int r0 = q0 + rb;
            #pragma unroll
            for (int nt = 0; nt < 8; nt++) {
                const int c0 = k0 + nt * 8 + 2 * cc;
                if (c0     > r0    ) s[nt][0] = -1e30f;
                if (c0 + 1 > r0    ) s[nt][1] = -1e30f;
                if (c0     > r0 + 8) s[nt][2] = -1e30f;
                if (c0 + 1 > r0 + 8) s[nt][3] = -1e30f;
            }
        }

        // Online softmax (rows g and g+8; reduce across the 4-lane quad)
        #pragma unroll
        for (int hr = 0; hr < 2; hr++) {
            float mt = -1e30f;
            #pragma unroll
            for (int nt = 0; nt < 8; nt++)
                mt = fmaxf(mt, fmaxf(s[nt][hr * 2], s[nt][hr * 2 + 1]));
            mt = fmaxf(mt, __shfl_xor_sync(0xffffffffu, mt, 1));
            mt = fmaxf(mt, __shfl_xor_sync(0xffffffffu, mt, 2));
            const float mnew  = fmaxf(m_i[hr], mt);
            const float alpha = __expf(m_i[hr] - mnew);
            m_i[hr] = mnew;
            float rs = 0.f;
            #pragma unroll
            for (int nt = 0; nt < 8; nt++) {
                const float p0 = __expf(s[nt][hr * 2]     - mnew);
                const float p1 = __expf(s[nt][hr * 2 + 1] - mnew);
                s[nt][hr * 2]     = p0;
                s[nt][hr * 2 + 1] = p1;
                rs += p0 + p1;
            }
            rs += __shfl_xor_sync(0xffffffffu, rs, 1);
            rs += __shfl_xor_sync(0xffffffffu, rs, 2);
            l_i[hr] = l_i[hr] * alpha + rs;
            #pragma unroll
            for (int nt = 0; nt < 8; nt++) {
                o[nt][hr * 2]     *= alpha;
                o[nt][hr * 2 + 1] *= alpha;
            }
        }

        // Stage P^T (each warp writes & reads only its own 16 columns)
        #pragma unroll
        for (int nt = 0; nt < 8; nt++) {
            const int c0 = nt * 8 + 2 * cc;
            sP[(c0    ) * PSTR + rb    ] = __uint_as_float(f2tf(s[nt][0]));
            sP[(c0 + 1) * PSTR + rb    ] = __uint_as_float(f2tf(s[nt][1]));
            sP[(c0    ) * PSTR + rb + 8] = __uint_as_float(f2tf(s[nt][2]));
            sP[(c0 + 1) * PSTR + rb + 8] = __uint_as_float(f2tf(s[nt][3]));
        }
        __syncwarp();

        // O += P @ V via mma
        #pragma unroll
        for (int k8 = 0; k8 < KT; k8 += 8) {
            const unsigned a0 = __float_as_uint(sP[(k8 + cc    ) * PSTR + rb    ]);
            const unsigned a1 = __float_as_uint(sP[(k8 + cc    ) * PSTR + rb + 8]);
            const unsigned a2 = __float_as_uint(sP[(k8 + cc + 4) * PSTR + rb    ]);
            const unsigned a3 = __float_as_uint(sP[(k8 + cc + 4) * PSTR + rb + 8]);
            #pragma unroll
            for (int nt = 0; nt < 8; nt++) {
                const unsigned b0 = __float_as_uint(sV[(k8 + cc    ) * VSTR + nt * 8 + g]);
                const unsigned b1 = __float_as_uint(sV[(k8 + cc + 4) * VSTR + nt * 8 + g]);
                mma_tf32(o[nt], a0, a1, a2, a3, b0, b1);
            }
        }
    }

    // Epilogue: normalize + write concat-heads [B,S,C]
    const int b = bh >> 4;
    const int h = bh & (Hn - 1);
    #pragma unroll
    for (int hr = 0; hr < 2; hr++) {
        const float inv = 1.f / l_i[hr];
        const int row = q0 + rb + hr * 8;
        #pragma unroll
        for (int nt = 0; nt < 8; nt++) {
            float2 ov = make_float2(o[nt][hr * 2] * inv, o[nt][hr * 2 + 1] * inv);
            *(float2*)(g_att + ((size_t)b * Ssz + row) * Csz
                       + h * HSz + nt * 8 + 2 * cc) = ov;
        }
    }
}

// ---------------------------------------------------------------------------
// Kernel 3: output projection, tf32 tensor cores, 2-stage smem pipeline.
// ---------------------------------------------------------------------------
__global__ __launch_bounds__(256)
void proj_kernel(const float* __restrict__ Wp,
                 const float* __restrict__ bp,
                 float* __restrict__ out)
{
    __shared__ float sA[2][16][SSTR];
    __shared__ float sB[2][16][SSTR];

    const int tid  = threadIdx.x;
    const int lane = tid & 31;
    const int g    = lane >> 2;
    const int cc   = lane & 3;
    const int wid  = tid >> 5;
    const int wm   = wid & 1;
    const int wn   = wid >> 1;

    const int m0 = blockIdx.y * 128;
    const int n0 = blockIdx.x * 128;

    const int a_row = tid >> 1;
    const int a_k8  = (tid & 1) << 3;
    const float* aptr = g_att + (size_t)(m0 + a_row) * Csz + a_k8;
    const float* bptr = Wp    + (size_t)(n0 + a_row) * Csz + a_k8;

    float acc[4][4][4];
    #pragma unroll
    for (int i = 0; i < 4; i++)
        #pragma unroll
        for (int j = 0; j < 4; j++)
            #pragma unroll
            for (int r = 0; r < 4; r++) acc[i][j][r] = 0.f;

    float4 pa0 = *(const float4*)(aptr);
    float4 pa1 = *(const float4*)(aptr + 4);
    float4 pb0 = *(const float4*)(bptr);
    float4 pb1 = *(const float4*)(bptr + 4);

    sA[0][a_k8 + 0][a_row] = __uint_as_float(f2tf(pa0.x));
    sA[0][a_k8 + 1][a_row] = __uint_as_float(f2tf(pa0.y));
    sA[0][a_k8 + 2][a_row] = __uint_as_float(f2tf(pa0.z));
    sA[0][a_k8 + 3][a_row] = __uint_as_float(f2tf(pa0.w));
    sA[0][a_k8 + 4][a_row] = __uint_as_float(f2tf(pa1.x));
    sA[0][a_k8 + 5][a_row] = __uint_as_float(f2tf(pa1.y));
    sA[0][a_k8 + 6][a_row] = __uint_as_float(f2tf(pa1.z));
    sA[0][a_k8 + 7][a_row] = __uint_as_float(f2tf(pa1.w));
    sB[0][a_k8 + 0][a_row] = __uint_as_float(f2tf(pb0.x));
    sB[0][a_k8 + 1][a_row] = __uint_as_float(f2tf(pb0.y));
    sB[0][a_k8 + 2][a_row] = __uint_as_float(f2tf(pb0.z));
    sB[0][a_k8 + 3][a_row] = __uint_as_float(f2tf(pb0.w));
    sB[0][a_k8 + 4][a_row] = __uint_as_float(f2tf(pb1.x));
    sB[0][a_k8 + 5][a_row] = __uint_as_float(f2tf(pb1.y));
    sB[0][a_k8 + 6][a_row] = __uint_as_float(f2tf(pb1.z));
    sB[0][a_k8 + 7][a_row] = __uint_as_float(f2tf(pb1.w));
    __syncthreads();

    for (int k0 = 0; k0 < Csz; k0 += 16) {
        const int p = (k0 >> 4) & 1;
        const bool more = (k0 + 16) < Csz;

        if (more) {
            pa0 = *(const float4*)(aptr + k0 + 16);
            pa1 = *(const float4*)(aptr + k0 + 20);
            pb0 = *(const float4*)(bptr + k0 + 16);
            pb1 = *(const float4*)(bptr + k0 + 20);
        }

        #pragma unroll
        for (int k8 = 0; k8 < 16; k8 += 8) {
            unsigned af[4][4], bf[4][2];
            #pragma unroll
            for (int mt = 0; mt < 4; mt++) {
                const int rbm = wm * 64 + mt * 16 + g;
                af[mt][0] = __float_as_uint(sA[p][k8 + cc    ][rbm    ]);
                af[mt][1] = __float_as_uint(sA[p][k8 + cc    ][rbm + 8]);
                af[mt][2] = __float_as_uint(sA[p][k8 + cc + 4][rbm    ]);
                af[mt][3] = __float_as_uint(sA[p][k8 + cc + 4][rbm + 8]);
            }
            #pragma unroll
            for (int nt = 0; nt < 4; nt++) {
                const int nbi = wn * 32 + nt * 8 + g;
                bf[nt][0] = __float_as_uint(sB[p][k8 + cc    ][nbi]);
                bf[nt][1] = __float_as_uint(sB[p][k8 + cc + 4][nbi]);
            }
            #pragma unroll
            for (int mt = 0; mt < 4; mt++)
                #pragma unroll
                for (int nt = 0; nt < 4; nt++)
                    mma_tf32(acc[mt][nt], af[mt][0], af[mt][1], af[mt][2], af[mt][3],
                             bf[nt][0], bf[nt][1]);
        }

        if (more) {
            const int q = p ^ 1;
            sA[q][a_k8 + 0][a_row] = __uint_as_float(f2tf(pa0.x));
            sA[q][a_k8 + 1][a_row] = __uint_as_float(f2tf(pa0.y));
            sA[q][a_k8 + 2][a_row] = __uint_as_float(f2tf(pa0.z));
            sA[q][a_k8 + 3][a_row] = __uint_as_float(f2tf(pa0.w));
            sA[q][a_k8 + 4][a_row] = __uint_as_float(f2tf(pa1.x));
            sA[q][a_k8 + 5][a_row] = __uint_as_float(f2tf(pa1.y));
            sA[q][a_k8 + 6][a_row] = __uint_as_float(f2tf(pa1.z));
            sA[q][a_k8 + 7][a_row] = __uint_as_float(f2tf(pa1.w));
            sB[q][a_k8 + 0][a_row] = __uint_as_float(f2tf(pb0.x));
            sB[q][a_k8 + 1][a_row] = __uint_as_float(f2tf(pb0.y));
            sB[q][a_k8 + 2][a_row] = __uint_as_float(f2tf(pb0.z));
            sB[q][a_k8 + 3][a_row] = __uint_as_float(f2tf(pb0.w));
            sB[q][a_k8 + 4][a_row] = __uint_as_float(f2tf(pb1.x));
            sB[q][a_k8 + 5][a_row] = __uint_as_float(f2tf(pb1.y));
            sB[q][a_k8 + 6][a_row] = __uint_as_float(f2tf(pb1.z));
            sB[q][a_k8 + 7][a_row] = __uint_as_float(f2tf(pb1.w));
        }
        __syncthreads();
    }

    #pragma unroll
    for (int nt = 0; nt < 4; nt++) {
        const int n = n0 + wn * 32 + nt * 8 + 2 * cc;
        const float2 bias = *(const float2*)(bp + n);
        #pragma unroll
        for (int mt = 0; mt < 4; mt++) {
            const int m = m0 + wm * 64 + mt * 16 + g;
            float* base = out + (size_t)m * Csz + n;
            *(float2*)base = make_float2(acc[mt][nt][0] + bias.x,
                                         acc[mt][nt][1] + bias.y);
            *(float2*)(base + 8 * Csz) = make_float2(acc[mt][nt][2] + bias.x,
                                                     acc[mt][nt][3] + bias.y);
        }
    }
}

// ---------------------------------------------------------------------------
extern "C" void kernel_launch(void* const* d_in, const int* in_sizes, int n_in,
                              void* d_out, int out_size)
{
    const float* x  = (const float*)d_in[0];
    const float* Wq = (const float*)d_in[1];
    const float* Wk = (const float*)d_in[2];
    const float* Wv = (const float*)d_in[3];
    const float* Wp = (const float*)d_in[4];
    const float* bp = (const float*)d_in[5];
    float* out = (float*)d_out;

    const int attn_smem = (HSz * PSTR + KT * PSTR + HSz * VSTR + KT * VSTR)
                          * (int)sizeof(float);   // 106496 B
    cudaFuncSetAttribute(attn_kernel,
                         cudaFuncAttributeMaxDynamicSharedMemorySize, attn_smem);

    // QKV: N=3072, M=8192
    qkv_gemm_kernel<<<dim3(3072 / 128, 8192 / 128), 256>>>(x, Wq, Wk, Wv);
    // Attention: 16 q-tiles (128 rows each) x 64 (b,h)
    attn_kernel<<<dim3(Ssz / QT, Bsz * Hn), 256, attn_smem>>>();
    // Projection: N=1024, M=8192
    proj_kernel<<<dim3(Csz / 128, 8192 / 128), 256>>>(Wp, bp, out);
}